// round 8
// baseline (speedup 1.0000x reference)
#include <cuda_runtime.h>
#include <math.h>

#define TT 4096
#define EE 512
#define HH 512

// ---------------- scratch (static device globals; no allocation) ----------------
__device__ float g_e[TT];
__device__ float g_xpf[(size_t)TT * 1536];
__device__ float g_xpb[(size_t)TT * 1536];
__device__ float g_out[(size_t)TT * 1024];     // [t][2H]  (fwd 0..511, bwd 512..1023)
__device__ float g_hid[1024];
__device__ float g_logits[TT];
__device__ unsigned g_rdy[2][32];              // per-direction 128-row-block ready counters

// ---------------- helpers ----------------
__device__ __forceinline__ float fsig(float x) {
    return __fdividef(1.f, 1.f + __expf(-x));
}
__device__ __forceinline__ float ftanh_fast(float x) {
    float t = __expf(-2.f * x);
    return __fdividef(1.f - t, 1.f + t);
}
__device__ __forceinline__ unsigned smem_u32(const void* p) {
    unsigned a;
    asm("{ .reg .u64 t; cvta.to.shared.u64 t, %1; cvt.u32.u64 %0, t; }" : "=r"(a) : "l"(p));
    return a;
}
__device__ __forceinline__ unsigned long long lds_vol_u64(unsigned a) {
    unsigned long long v;
    asm volatile("ld.volatile.shared.u64 %0, [%1];" : "=l"(v) : "r"(a));
    return v;
}
__device__ __forceinline__ void fma2(unsigned long long& acc, unsigned long long a,
                                     unsigned long long b) {
    asm("fma.rn.f32x2 %0, %1, %2, %0;" : "+l"(acc) : "l"(a), "l"(b));
}
__device__ __forceinline__ unsigned ldacq32(const unsigned* p) {
    unsigned v;
    asm volatile("ld.acquire.gpu.global.u32 %0, [%1];" : "=r"(v) : "l"(p));
    return v;
}

// ---------------- e[t] = dot(query[t], fc_w) + fc_b  (also zeroes g_rdy) --------
__global__ void k_e(const float* __restrict__ q, const float* __restrict__ fcw,
                    const float* __restrict__ fcb) {
    if (blockIdx.x == 0 && threadIdx.x < 64) ((unsigned*)g_rdy)[threadIdx.x] = 0u;
    int t = blockIdx.x * 8 + (threadIdx.x >> 5);
    int l = threadIdx.x & 31;
    const float* row = q + (size_t)t * EE;
    float s = 0.f;
    #pragma unroll
    for (int i = 0; i < 16; i++) s += row[l + 32 * i] * fcw[l + 32 * i];
    #pragma unroll
    for (int o = 16; o; o >>= 1) s += __shfl_down_sync(0xffffffffu, s, o);
    if (l == 0) g_e[t] = s + fcb[0];
}

__global__ void k_diag(float* __restrict__ out) {
    int i = blockIdx.x * blockDim.x + threadIdx.x;
    if (i < TT) out[1024 + (size_t)i * (TT + 1)] = g_e[i];
}

// ---------------- fused kernel: cluster GRU (blocks 0-31) + GEMM/zero workers (32-127) ----
// grid = 128 CTAs x 512 threads, cluster 16 -> 8 clusters, all resident in one wave.
// GRU identical to the R7 winner, plus an acquire-gate on xp row-blocks.
// Workers produce xp tiles in consumption order (fwd ascending / bwd descending blocks,
// interleaved), flag each 128-row block with a release add, then zero the energy plane.
__global__ void __launch_bounds__(512, 1) __cluster_dims__(16, 1, 1)
k_fused(const float* __restrict__ input,
        const float* __restrict__ wihf, const float* __restrict__ bihf,
        const float* __restrict__ wihb, const float* __restrict__ bihb,
        const float* __restrict__ whhf, const float* __restrict__ bhhf,
        const float* __restrict__ whhb, const float* __restrict__ bhhb,
        float* __restrict__ out, int n4) {
    int bid = blockIdx.x;
    int tid = threadIdx.x;

    if (bid >= 32) {
        // ================= GEMM worker =================
        __shared__ float As[16][128];
        __shared__ float Bs[16][64];
        int wb = bid - 32;                     // 0..95
        int aRow = tid >> 2;                   // 0..127
        int aCol = (tid & 3) * 4;              // 0,4,8,12
        int tx = tid & 15, ty = tid >> 4;      // tile 4(n) x 4(m) per thread

        for (int job = wb; job < 1536; job += 96) {
            int p = job / 48;                  // 0..31  (pair index)
            int q = job % 48;
            int dirj = (q >= 24);
            int mb = dirj ? (31 - p) : p;      // fwd ascending, bwd descending
            int ct = dirj ? (q - 24) : q;
            const float* W = dirj ? wihb : wihf;
            const float* bias = dirj ? bihb : bihf;
            float* Co = dirj ? g_xpb : g_xpf;
            int m0 = mb * 128, n0 = ct * 64;
            float ea = g_e[m0 + aRow];

            float acc[4][4];
            #pragma unroll
            for (int i = 0; i < 4; i++)
                #pragma unroll
                for (int jj = 0; jj < 4; jj++) acc[i][jj] = 0.f;

            for (int k0 = 0; k0 < EE; k0 += 16) {
                float4 a0 = *(const float4*)(input + (size_t)(m0 + aRow) * EE + k0 + aCol);
                float4 b0 = make_float4(0.f, 0.f, 0.f, 0.f);
                if (tid < 256)
                    b0 = *(const float4*)(W + (size_t)(n0 + aRow) * EE + k0 + aCol);
                __syncthreads();
                As[aCol + 0][aRow] = a0.x * ea; As[aCol + 1][aRow] = a0.y * ea;
                As[aCol + 2][aRow] = a0.z * ea; As[aCol + 3][aRow] = a0.w * ea;
                if (tid < 256) {
                    Bs[aCol + 0][aRow] = b0.x; Bs[aCol + 1][aRow] = b0.y;
                    Bs[aCol + 2][aRow] = b0.z; Bs[aCol + 3][aRow] = b0.w;
                }
                __syncthreads();
                #pragma unroll
                for (int kk = 0; kk < 16; kk++) {
                    float4 av = *(float4*)&As[kk][ty * 4];
                    float4 bv = *(float4*)&Bs[kk][tx * 4];
                    float am[4] = {av.x, av.y, av.z, av.w};
                    float bn[4] = {bv.x, bv.y, bv.z, bv.w};
                    #pragma unroll
                    for (int i = 0; i < 4; i++)
                        #pragma unroll
                        for (int jj = 0; jj < 4; jj++) acc[i][jj] += am[i] * bn[jj];
                }
            }
            float bb0 = bias[n0 + tx * 4 + 0], bb1 = bias[n0 + tx * 4 + 1];
            float bb2 = bias[n0 + tx * 4 + 2], bb3 = bias[n0 + tx * 4 + 3];
            #pragma unroll
            for (int i = 0; i < 4; i++) {
                int m = m0 + ty * 4 + i;
                float4 v = make_float4(acc[i][0] + bb0, acc[i][1] + bb1,
                                       acc[i][2] + bb2, acc[i][3] + bb3);
                *(float4*)(Co + (size_t)m * 1536 + n0 + tx * 4) = v;
            }
            // release: all threads' tile stores visible before the block counter bump
            __threadfence();
            __syncthreads();
            if (tid == 0)
                asm volatile("red.release.gpu.global.add.u32 [%0], 1;"
                             :: "l"(&g_rdy[dirj][mb]));
        }
        // ---- zero the energy plane (runs in GRU shadow; done before k_diag launch) ----
        float4 z = make_float4(0.f, 0.f, 0.f, 0.f);
        float4* pz = (float4*)(out + 1024);
        for (int i = wb * 512 + tid; i < n4; i += 96 * 512) pz[i] = z;
        return;
    }

    // ================= cluster GRU (identical to R7 winner + block gate) =================
    __shared__ unsigned long long tagbuf[2][HH];  // [parity][h]: hi=tag, lo=float bits
    __shared__ float hs[HH];

    int dir = bid >> 4;
    unsigned rank = bid & 15;
    const float* whh = dir ? whhb : whhf;
    const float* bhh = dir ? bhhb : bhhf;
    const float* xp  = dir ? g_xpb : g_xpf;

    int w = tid >> 5, l = tid & 31;
    int hw = l >> 4, l2 = l & 15;
    int j = (int)rank * 32 + 2 * w + hw;   // this half-warp's global h index

    tagbuf[0][tid] = 0ull;                     // tag 0, h=0 (state before step 0)
    tagbuf[1][tid] = 0xFFFFFFFF00000000ull;    // invalid
    __syncthreads();
    asm volatile("barrier.cluster.arrive.aligned;" ::: "memory");
    asm volatile("barrier.cluster.wait.aligned;" ::: "memory");

    unsigned long long wr[3][16];
    #pragma unroll
    for (int g = 0; g < 3; g++) {
        const float* row = whh + (size_t)(g * 512 + j) * 512;
        #pragma unroll
        for (int c = 0; c < 8; c++) {
            ulonglong2 v = *(const ulonglong2*)(row + c * 64 + l2 * 4);
            wr[g][c * 2 + 0] = v.x;
            wr[g][c * 2 + 1] = v.y;
        }
    }
    float bh0 = bhh[j], bh1 = bhh[512 + j], bh2 = bhh[1024 + j];
    float hold = 0.f;

    unsigned tb_base = smem_u32(&tagbuf[0][0]);
    int cur_blk = -1;

    // gate + prefetch xp row for t=0
    float xr_c, xz_c, xn_c;
    {
        int row0 = dir ? (TT - 1) : 0;
        int nb = row0 >> 7;
        while (ldacq32(&g_rdy[dir][nb]) < 24u) {}
        cur_blk = nb;
        const float* rp = xp + (size_t)row0 * 1536;
        xr_c = __ldg(rp + j);
        xz_c = __ldg(rp + 512 + j);
        xn_c = __ldg(rp + 1024 + j);
    }

    for (int t = 0; t < TT; t++) {
        // gate + issue xp loads for step t+1 (consumed next iteration)
        int tn = (t + 1 < TT) ? (t + 1) : t;
        int rowp = dir ? (TT - 1 - tn) : tn;
        int nb = rowp >> 7;
        if (nb != cur_blk) {
            while (ldacq32(&g_rdy[dir][nb]) < 24u) {}
            cur_blk = nb;
        }
        const float* xprow = xp + (size_t)rowp * 1536;
        float xr_n = __ldg(xprow + j);
        float xz_n = __ldg(xprow + 512 + j);
        float xn_n = __ldg(xprow + 1024 + j);

        // poll own slot in LOCAL smem until tag == t
        unsigned slot = tb_base + ((t & 1) ? 4096u : 0u) + (unsigned)tid * 8u;
        unsigned tg = (unsigned)t;
        unsigned long long v = lds_vol_u64(slot);
        while ((unsigned)(v >> 32) != tg) v = lds_vol_u64(slot);
        hs[tid] = __uint_as_float((unsigned)v);
        __syncthreads();

        // matvec via packed f32x2 FMA
        unsigned long long a0p = 0ull, a1p = 0ull, a2p = 0ull;
        const ulonglong2* hp = (const ulonglong2*)hs;
        #pragma unroll
        for (int c = 0; c < 8; c++) {
            ulonglong2 hv = hp[(c * 64 + l2 * 4) >> 2];
            fma2(a0p, wr[0][c*2+0], hv.x); fma2(a0p, wr[0][c*2+1], hv.y);
            fma2(a1p, wr[1][c*2+0], hv.x); fma2(a1p, wr[1][c*2+1], hv.y);
            fma2(a2p, wr[2][c*2+0], hv.x); fma2(a2p, wr[2][c*2+1], hv.y);
        }
        float a0 = __uint_as_float((unsigned)a0p) + __uint_as_float((unsigned)(a0p >> 32));
        float a1 = __uint_as_float((unsigned)a1p) + __uint_as_float((unsigned)(a1p >> 32));
        float a2 = __uint_as_float((unsigned)a2p) + __uint_as_float((unsigned)(a2p >> 32));
        #pragma unroll
        for (int o = 8; o; o >>= 1) {
            a0 += __shfl_xor_sync(0xffffffffu, a0, o, 16);
            a1 += __shfl_xor_sync(0xffffffffu, a1, o, 16);
            a2 += __shfl_xor_sync(0xffffffffu, a2, o, 16);
        }
        float r = fsig(xr_c + bh0 + a0);
        float z = fsig(xz_c + bh1 + a1);
        float n = ftanh_fast(__fmaf_rn(r, a2 + bh2, xn_c));
        float hnew = __fmaf_rn(z, hold - n, n);   // (1-z)*n + z*h
        hold = hnew;
        if (t + 1 < TT) {
            // lane l2 pushes {tag t+1, hnew} to rank l2: 16-way fan-out, one instruction
            unsigned long long pv = ((unsigned long long)(unsigned)(t + 1) << 32) |
                                    (unsigned long long)__float_as_uint(hnew);
            unsigned loff = tb_base + (((t + 1) & 1) ? 4096u : 0u) + (unsigned)j * 8u;
            unsigned raddr;
            asm("mapa.shared::cluster.u32 %0, %1, %2;"
                : "=r"(raddr) : "r"(loff), "r"((unsigned)l2));
            asm volatile("st.shared::cluster.u64 [%0], %1;"
                         :: "r"(raddr), "l"(pv) : "memory");
        }
        if (l2 == 0) {
            int orow = dir ? (TT - 1 - t) : t;
            g_out[(size_t)orow * 1024 + dir * 512 + j] = hnew;
        }
        xr_c = xr_n; xz_c = xz_n; xn_c = xn_n;
        __syncthreads();   // hs reads of step t complete before any t+1 write; lockstep
    }
    asm volatile("barrier.cluster.arrive.aligned;" ::: "memory");
    asm volatile("barrier.cluster.wait.aligned;" ::: "memory");
}

// ---------------- attention epilogue ----------------
__global__ void k_hid() {
    int i = blockIdx.x * blockDim.x + threadIdx.x;
    if (i < 512) g_hid[i] = g_out[512 + i];                                // hb_last
    else if (i < 1024) g_hid[i] = g_out[(size_t)4095 * 1024 + (i - 512)];  // hf_last
}

__global__ void k_logits() {
    int t = blockIdx.x * 8 + (threadIdx.x >> 5);
    int l = threadIdx.x & 31;
    const float* row = g_out + (size_t)t * 1024;
    float s = 0.f;
    #pragma unroll
    for (int i = 0; i < 32; i++) s += row[l + 32 * i] * g_hid[l + 32 * i];
    #pragma unroll
    for (int o = 16; o; o >>= 1) s += __shfl_down_sync(0xffffffffu, s, o);
    if (l == 0) g_logits[t] = s * 0.03125f;  // 1/sqrt(1024)
}

__global__ void k_softmax() {
    __shared__ float red1[32], red2[32];
    int tid = threadIdx.x;
    float m = -1e30f;
    for (int i = tid; i < TT; i += 1024) m = fmaxf(m, g_logits[i]);
    #pragma unroll
    for (int o = 16; o; o >>= 1) m = fmaxf(m, __shfl_xor_sync(0xffffffffu, m, o));
    if ((tid & 31) == 0) red1[tid >> 5] = m;
    __syncthreads();
    if (tid < 32) {
        float v = red1[tid];
        #pragma unroll
        for (int o = 16; o; o >>= 1) v = fmaxf(v, __shfl_xor_sync(0xffffffffu, v, o));
        if (tid == 0) red1[0] = v;
    }
    __syncthreads();
    m = red1[0];
    float s = 0.f;
    for (int i = tid; i < TT; i += 1024) s += expf(g_logits[i] - m);
    #pragma unroll
    for (int o = 16; o; o >>= 1) s += __shfl_xor_sync(0xffffffffu, s, o);
    if ((tid & 31) == 0) red2[tid >> 5] = s;
    __syncthreads();
    if (tid < 32) {
        float v = red2[tid];
        #pragma unroll
        for (int o = 16; o; o >>= 1) v += __shfl_xor_sync(0xffffffffu, v, o);
        if (tid == 0) red2[0] = v;
    }
    __syncthreads();
    float inv = 1.f / red2[0];
    for (int i = tid; i < TT; i += 1024) g_logits[i] = expf(g_logits[i] - m) * inv;
}

__global__ void k_lin(float* __restrict__ out) {
    int c = blockIdx.x;
    int jj = threadIdx.x & 63;
    int rr = threadIdx.x >> 6;
    int col = c * 64 + jj;
    float acc = 0.f;
    for (int t = rr; t < TT; t += 4) acc += g_logits[t] * g_out[(size_t)t * 1024 + col];
    __shared__ float sm[4][64];
    sm[rr][jj] = acc;
    __syncthreads();
    if (rr == 0) out[col] = sm[0][jj] + sm[1][jj] + sm[2][jj] + sm[3][jj];
}

// ---------------- launch ----------------
extern "C" void kernel_launch(void* const* d_in, const int* in_sizes, int n_in,
                              void* d_out, int out_size) {
    const float* input = (const float*)d_in[0];
    const float* query = (const float*)d_in[1];
    const float* fc_w  = (const float*)d_in[2];
    const float* fc_b  = (const float*)d_in[3];
    const float* wihf  = (const float*)d_in[4];
    const float* whhf  = (const float*)d_in[5];
    const float* bihf  = (const float*)d_in[6];
    const float* bhhf  = (const float*)d_in[7];
    const float* wihb  = (const float*)d_in[8];
    const float* whhb  = (const float*)d_in[9];
    const float* bihb  = (const float*)d_in[10];
    const float* bhhb  = (const float*)d_in[11];
    float* out = (float*)d_out;

    int n4 = (out_size - 1024) / 4;  // energy float4 count

    cudaFuncSetAttribute(k_fused, cudaFuncAttributeNonPortableClusterSizeAllowed, 1);

    k_e<<<TT / 8, 256>>>(query, fc_w, fc_b);
    k_fused<<<128, 512>>>(input, wihf, bihf, wihb, bihb,
                          whhf, bhhf, whhb, bhhb, out, n4);
    k_diag<<<16, 256>>>(out);
    k_hid<<<4, 256>>>();
    k_logits<<<TT / 8, 256>>>();
    k_softmax<<<1, 1024>>>();
    k_lin<<<16, 256>>>(out);
}

// round 9
// speedup vs baseline: 1.4362x; 1.4362x over previous
#include <cuda_runtime.h>
#include <math.h>

#define TT 4096
#define EE 512
#define HH 512

// ---------------- scratch (static device globals; no allocation) ----------------
__device__ float g_e[TT];
__device__ float g_xpf[(size_t)TT * 1536];
__device__ float g_xpb[(size_t)TT * 1536];
__device__ float g_out[(size_t)TT * 1024];     // [t][2H]  (fwd 0..511, bwd 512..1023)
__device__ float g_hid[1024];
__device__ float g_logits[TT];

// ---------------- helpers ----------------
__device__ __forceinline__ float fsig(float x) {
    return __fdividef(1.f, 1.f + __expf(-x));
}
__device__ __forceinline__ float ftanh_fast(float x) {
    float t = __expf(-2.f * x);
    return __fdividef(1.f - t, 1.f + t);
}
__device__ __forceinline__ unsigned smem_u32(const void* p) {
    unsigned a;
    asm("{ .reg .u64 t; cvta.to.shared.u64 t, %1; cvt.u32.u64 %0, t; }" : "=r"(a) : "l"(p));
    return a;
}
__device__ __forceinline__ unsigned long long lds_vol_u64(unsigned a) {
    unsigned long long v;
    asm volatile("ld.volatile.shared.u64 %0, [%1];" : "=l"(v) : "r"(a));
    return v;
}
__device__ __forceinline__ void fma2(unsigned long long& acc, unsigned long long a,
                                     unsigned long long b) {
    asm("fma.rn.f32x2 %0, %1, %2, %0;" : "+l"(acc) : "l"(a), "l"(b));
}
__device__ __forceinline__ unsigned long long pack2(float lo, float hi) {
    unsigned long long v;
    asm("mov.b64 %0, {%1, %2};" : "=l"(v) : "f"(lo), "f"(hi));
    return v;
}
__device__ __forceinline__ float lo32(unsigned long long v) {
    return __uint_as_float((unsigned)v);
}
__device__ __forceinline__ float hi32(unsigned long long v) {
    return __uint_as_float((unsigned)(v >> 32));
}

// ---------------- e[t] = dot(query[t], fc_w) + fc_b ----------------
__global__ void k_e(const float* __restrict__ q, const float* __restrict__ fcw,
                    const float* __restrict__ fcb) {
    int t = blockIdx.x * 8 + (threadIdx.x >> 5);
    int l = threadIdx.x & 31;
    const float* row = q + (size_t)t * EE;
    float s = 0.f;
    #pragma unroll
    for (int i = 0; i < 16; i++) s += row[l + 32 * i] * fcw[l + 32 * i];
    #pragma unroll
    for (int o = 16; o; o >>= 1) s += __shfl_down_sync(0xffffffffu, s, o);
    if (l == 0) g_e[t] = s + fcb[0];
}

// ---------------- energy: zero fill then diagonal (AFTER the GRU -> xp stays L2-hot) ----
__global__ void k_zero(float* __restrict__ out, int n4) {
    float4 z = make_float4(0.f, 0.f, 0.f, 0.f);
    float4* p = (float4*)(out + 1024);
    int stride = gridDim.x * blockDim.x;
    for (int i = blockIdx.x * blockDim.x + threadIdx.x; i < n4; i += stride) p[i] = z;
}
__global__ void k_diag(float* __restrict__ out) {
    int i = blockIdx.x * blockDim.x + threadIdx.x;
    if (i < TT) out[1024 + (size_t)i * (TT + 1)] = g_e[i];
}

// ---------------- GEMM (f32x2 inner): Co[t][n] = sum_k (e[t]*A[t][k])*W[n][k] + b[n] -------
// BM=128, BN=64, BK=16, 256 threads, thread tile 8m x 4n; acc held as 8x2 f32x2 pairs.
// B pairs come directly from the float4 smem layout; A elements duplicated via mov.b64
// on the ALU pipe (overlaps the FMA pipe). FMA-pipe instructions halve vs scalar FFMA.
__global__ void __launch_bounds__(256) k_gemm2(const float* __restrict__ A,
                                               const float* __restrict__ Wf,
                                               const float* __restrict__ bf,
                                               const float* __restrict__ Wb,
                                               const float* __restrict__ bbp) {
    int which = blockIdx.z;
    const float* __restrict__ W = which ? Wb : Wf;
    const float* __restrict__ bias = which ? bbp : bf;
    float* __restrict__ Co = which ? g_xpb : g_xpf;
    __shared__ __align__(16) float As[16][128];
    __shared__ __align__(16) float Bs[16][64];
    int tid = threadIdx.x;
    int tx = tid & 15, ty = tid >> 4;
    int m0 = blockIdx.y * 128, n0 = blockIdx.x * 64;

    int aRow = tid >> 2;
    int aCol = (tid & 3) * 4;
    float e0 = g_e[m0 + aRow];
    float e1 = g_e[m0 + aRow + 64];

    unsigned long long acc2[8][2];
    #pragma unroll
    for (int i = 0; i < 8; i++) { acc2[i][0] = 0ull; acc2[i][1] = 0ull; }

    for (int k0 = 0; k0 < EE; k0 += 16) {
        float4 a0 = *(const float4*)(A + (size_t)(m0 + aRow) * EE + k0 + aCol);
        float4 a1 = *(const float4*)(A + (size_t)(m0 + aRow + 64) * EE + k0 + aCol);
        float4 b0 = *(const float4*)(W + (size_t)(n0 + aRow) * EE + k0 + aCol);
        __syncthreads();
        As[aCol + 0][aRow] = a0.x * e0; As[aCol + 1][aRow] = a0.y * e0;
        As[aCol + 2][aRow] = a0.z * e0; As[aCol + 3][aRow] = a0.w * e0;
        As[aCol + 0][aRow + 64] = a1.x * e1; As[aCol + 1][aRow + 64] = a1.y * e1;
        As[aCol + 2][aRow + 64] = a1.z * e1; As[aCol + 3][aRow + 64] = a1.w * e1;
        Bs[aCol + 0][aRow] = b0.x; Bs[aCol + 1][aRow] = b0.y;
        Bs[aCol + 2][aRow] = b0.z; Bs[aCol + 3][aRow] = b0.w;
        __syncthreads();
        #pragma unroll
        for (int kk = 0; kk < 16; kk++) {
            float4 av0 = *(float4*)&As[kk][ty * 8];
            float4 av1 = *(float4*)&As[kk][ty * 8 + 4];
            ulonglong2 bp = *(ulonglong2*)&Bs[kk][tx * 4];   // (b0,b1),(b2,b3)
            float am[8] = {av0.x, av0.y, av0.z, av0.w, av1.x, av1.y, av1.z, av1.w};
            #pragma unroll
            for (int i = 0; i < 8; i++) {
                unsigned long long ad = pack2(am[i], am[i]);  // ALU pipe
                fma2(acc2[i][0], ad, bp.x);
                fma2(acc2[i][1], ad, bp.y);
            }
        }
    }
    float bb0 = bias[n0 + tx * 4 + 0], bb1 = bias[n0 + tx * 4 + 1];
    float bb2 = bias[n0 + tx * 4 + 2], bb3 = bias[n0 + tx * 4 + 3];
    #pragma unroll
    for (int i = 0; i < 8; i++) {
        int m = m0 + ty * 8 + i;
        float4 v = make_float4(lo32(acc2[i][0]) + bb0, hi32(acc2[i][0]) + bb1,
                               lo32(acc2[i][1]) + bb2, hi32(acc2[i][1]) + bb3);
        *(float4*)(Co + (size_t)m * 1536 + n0 + tx * 4) = v;
    }
}

// ---------------- cluster GRU: DSMEM tagged push, local-SMEM poll, hs double-buffered -----
// grid = 32 CTAs, cluster(16): blocks 0-15 = forward, 16-31 = backward.
// 512 threads/CTA; CTA rank owns h[rank*32 .. +31]; each half-warp owns one h.
// Butterfly reduce -> all 16 lanes hold sums -> all compute gates -> lane l2 pushes the
// tagged word to rank l2 (16-way fan-out, one SIMT instruction).
// hs double-buffered on parity: slow-warp reads of hs[p] at step t are safe against
// writes (next write to hs[p] is at t+2, transitively ordered after this warp's t+1 push).
// -> only ONE __syncthreads per step.
__global__ void __launch_bounds__(512, 1) __cluster_dims__(16, 1, 1)
k_gruc(const float* __restrict__ whhf, const float* __restrict__ bhhf,
       const float* __restrict__ whhb, const float* __restrict__ bhhb) {
    __shared__ __align__(16) unsigned long long tagbuf[2][HH];
    __shared__ __align__(16) float hs[2][HH];

    int dir = blockIdx.x >> 4;
    unsigned rank = blockIdx.x & 15;
    const float* whh = dir ? whhb : whhf;
    const float* bhh = dir ? bhhb : bhhf;
    const float* xp  = dir ? g_xpb : g_xpf;

    int tid = threadIdx.x;
    int w = tid >> 5, l = tid & 31;
    int hw = l >> 4, l2 = l & 15;
    int j = (int)rank * 32 + 2 * w + hw;   // this half-warp's global h index

    tagbuf[0][tid] = 0ull;                     // tag 0, h=0 (state before step 0)
    tagbuf[1][tid] = 0xFFFFFFFF00000000ull;    // invalid
    __syncthreads();
    asm volatile("barrier.cluster.arrive.aligned;" ::: "memory");
    asm volatile("barrier.cluster.wait.aligned;" ::: "memory");

    // weights: lane l2 covers k = c*64 + l2*4 .. +3 (c=0..7), packed f32x2
    unsigned long long wr[3][16];
    #pragma unroll
    for (int g = 0; g < 3; g++) {
        const float* row = whh + (size_t)(g * 512 + j) * 512;
        #pragma unroll
        for (int c = 0; c < 8; c++) {
            ulonglong2 v = *(const ulonglong2*)(row + c * 64 + l2 * 4);
            wr[g][c * 2 + 0] = v.x;
            wr[g][c * 2 + 1] = v.y;
        }
    }
    float bh0 = bhh[j], bh1 = bhh[512 + j], bh2 = bhh[1024 + j];
    float hold = 0.f;

    unsigned tb_base = smem_u32(&tagbuf[0][0]);

    // prefetch xp row for t=0
    float xr_c, xz_c, xn_c;
    {
        const float* row0 = xp + (size_t)(dir ? (TT - 1) : 0) * 1536;
        xr_c = __ldg(row0 + j);
        xz_c = __ldg(row0 + 512 + j);
        xn_c = __ldg(row0 + 1024 + j);
    }

    for (int t = 0; t < TT; t++) {
        // issue xp loads for step t+1 now; consumed next iteration
        int tn = (t + 1 < TT) ? (t + 1) : t;
        const float* xprow = xp + (size_t)(dir ? (TT - 1 - tn) : tn) * 1536;
        float xr_n = __ldg(xprow + j);
        float xz_n = __ldg(xprow + 512 + j);
        float xn_n = __ldg(xprow + 1024 + j);

        // poll own slot in LOCAL smem until tag == t
        int par = t & 1;
        unsigned slot = tb_base + (par ? 4096u : 0u) + (unsigned)tid * 8u;
        unsigned tg = (unsigned)t;
        unsigned long long v = lds_vol_u64(slot);
        while ((unsigned)(v >> 32) != tg) v = lds_vol_u64(slot);
        hs[par][tid] = __uint_as_float((unsigned)v);
        __syncthreads();   // the ONLY per-step barrier: hs[par] fully written before reads

        // matvec via packed f32x2 FMA
        unsigned long long a0p = 0ull, a1p = 0ull, a2p = 0ull;
        const ulonglong2* hp = (const ulonglong2*)hs[par];
        #pragma unroll
        for (int c = 0; c < 8; c++) {
            ulonglong2 hv = hp[(c * 64 + l2 * 4) >> 2];
            fma2(a0p, wr[0][c*2+0], hv.x); fma2(a0p, wr[0][c*2+1], hv.y);
            fma2(a1p, wr[1][c*2+0], hv.x); fma2(a1p, wr[1][c*2+1], hv.y);
            fma2(a2p, wr[2][c*2+0], hv.x); fma2(a2p, wr[2][c*2+1], hv.y);
        }
        float a0 = lo32(a0p) + hi32(a0p);
        float a1 = lo32(a1p) + hi32(a1p);
        float a2 = lo32(a2p) + hi32(a2p);
        // butterfly reduce width 16: ALL lanes end with the full sums
        #pragma unroll
        for (int o = 8; o; o >>= 1) {
            a0 += __shfl_xor_sync(0xffffffffu, a0, o, 16);
            a1 += __shfl_xor_sync(0xffffffffu, a1, o, 16);
            a2 += __shfl_xor_sync(0xffffffffu, a2, o, 16);
        }
        // all 16 lanes compute gates (SIMT); hold replicated per lane
        float r = fsig(xr_c + bh0 + a0);
        float z = fsig(xz_c + bh1 + a1);
        float n = ftanh_fast(__fmaf_rn(r, a2 + bh2, xn_c));
        float hnew = __fmaf_rn(z, hold - n, n);   // (1-z)*n + z*h
        hold = hnew;
        if (t + 1 < TT) {
            // lane l2 pushes {tag t+1, hnew} to rank l2: 16-way fan-out, one instruction
            unsigned long long pv = ((unsigned long long)(unsigned)(t + 1) << 32) |
                                    (unsigned long long)__float_as_uint(hnew);
            unsigned loff = tb_base + ((par ^ 1) ? 4096u : 0u) + (unsigned)j * 8u;
            unsigned raddr;
            asm("mapa.shared::cluster.u32 %0, %1, %2;"
                : "=r"(raddr) : "r"(loff), "r"((unsigned)l2));
            asm volatile("st.shared::cluster.u64 [%0], %1;"
                         :: "r"(raddr), "l"(pv) : "memory");
        }
        if (l2 == 0) {
            int orow = dir ? (TT - 1 - t) : t;
            g_out[(size_t)orow * 1024 + dir * 512 + j] = hnew;
        }
        xr_c = xr_n; xz_c = xz_n; xn_c = xn_n;
        // no trailing barrier: hs parity double-buffer makes t+1 writes race-free
    }
    asm volatile("barrier.cluster.arrive.aligned;" ::: "memory");
    asm volatile("barrier.cluster.wait.aligned;" ::: "memory");
}

// ---------------- attention epilogue ----------------
__global__ void k_hid() {
    int i = blockIdx.x * blockDim.x + threadIdx.x;
    if (i < 512) g_hid[i] = g_out[512 + i];                                // hb_last
    else if (i < 1024) g_hid[i] = g_out[(size_t)4095 * 1024 + (i - 512)];  // hf_last
}

__global__ void k_logits() {
    int t = blockIdx.x * 8 + (threadIdx.x >> 5);
    int l = threadIdx.x & 31;
    const float* row = g_out + (size_t)t * 1024;
    float s = 0.f;
    #pragma unroll
    for (int i = 0; i < 32; i++) s += row[l + 32 * i] * g_hid[l + 32 * i];
    #pragma unroll
    for (int o = 16; o; o >>= 1) s += __shfl_down_sync(0xffffffffu, s, o);
    if (l == 0) g_logits[t] = s * 0.03125f;  // 1/sqrt(1024)
}

__global__ void k_softmax() {
    __shared__ float red1[32], red2[32];
    int tid = threadIdx.x;
    float m = -1e30f;
    for (int i = tid; i < TT; i += 1024) m = fmaxf(m, g_logits[i]);
    #pragma unroll
    for (int o = 16; o; o >>= 1) m = fmaxf(m, __shfl_xor_sync(0xffffffffu, m, o));
    if ((tid & 31) == 0) red1[tid >> 5] = m;
    __syncthreads();
    if (tid < 32) {
        float v = red1[tid];
        #pragma unroll
        for (int o = 16; o; o >>= 1) v = fmaxf(v, __shfl_xor_sync(0xffffffffu, v, o));
        if (tid == 0) red1[0] = v;
    }
    __syncthreads();
    m = red1[0];
    float s = 0.f;
    for (int i = tid; i < TT; i += 1024) s += expf(g_logits[i] - m);
    #pragma unroll
    for (int o = 16; o; o >>= 1) s += __shfl_xor_sync(0xffffffffu, s, o);
    if ((tid & 31) == 0) red2[tid >> 5] = s;
    __syncthreads();
    if (tid < 32) {
        float v = red2[tid];
        #pragma unroll
        for (int o = 16; o; o >>= 1) v += __shfl_xor_sync(0xffffffffu, v, o);
        if (tid == 0) red2[0] = v;
    }
    __syncthreads();
    float inv = 1.f / red2[0];
    for (int i = tid; i < TT; i += 1024) g_logits[i] = expf(g_logits[i] - m) * inv;
}

__global__ void k_lin(float* __restrict__ out) {
    int c = blockIdx.x;
    int jj = threadIdx.x & 63;
    int rr = threadIdx.x >> 6;
    int col = c * 64 + jj;
    float acc = 0.f;
    for (int t = rr; t < TT; t += 4) acc += g_logits[t] * g_out[(size_t)t * 1024 + col];
    __shared__ float sm[4][64];
    sm[rr][jj] = acc;
    __syncthreads();
    if (rr == 0) out[col] = sm[0][jj] + sm[1][jj] + sm[2][jj] + sm[3][jj];
}

// ---------------- launch ----------------
extern "C" void kernel_launch(void* const* d_in, const int* in_sizes, int n_in,
                              void* d_out, int out_size) {
    const float* input = (const float*)d_in[0];
    const float* query = (const float*)d_in[1];
    const float* fc_w  = (const float*)d_in[2];
    const float* fc_b  = (const float*)d_in[3];
    const float* wihf  = (const float*)d_in[4];
    const float* whhf  = (const float*)d_in[5];
    const float* bihf  = (const float*)d_in[6];
    const float* bhhf  = (const float*)d_in[7];
    const float* wihb  = (const float*)d_in[8];
    const float* whhb  = (const float*)d_in[9];
    const float* bihb  = (const float*)d_in[10];
    const float* bhhb  = (const float*)d_in[11];
    float* out = (float*)d_out;

    int n4 = (out_size - 1024) / 4;  // energy float4 count

    cudaFuncSetAttribute(k_gruc, cudaFuncAttributeNonPortableClusterSizeAllowed, 1);

    k_e<<<TT / 8, 256>>>(query, fc_w, fc_b);
    dim3 gg(1536 / 64, TT / 128, 2);
    k_gemm2<<<gg, 256>>>(input, wihf, bihf, wihb, bihb);
    k_gruc<<<32, 512>>>(whhf, bhhf, whhb, bhhb);   // GRU owns the chip; xp L2-hot
    k_zero<<<4096, 256>>>(out, n4);                // 67MB streamed AFTER the GRU
    k_diag<<<16, 256>>>(out);
    k_hid<<<4, 256>>>();
    k_logits<<<TT / 8, 256>>>();
    k_softmax<<<1, 1024>>>();
    k_lin<<<16, 256>>>(out);
}

// round 10
// speedup vs baseline: 1.4404x; 1.0030x over previous
#include <cuda_runtime.h>
#include <math.h>

#define TT 4096
#define EE 512
#define HH 512

// ---------------- scratch (static device globals; no allocation) ----------------
__device__ float g_e[TT];
__device__ float g_xpf[(size_t)TT * 1536];
__device__ float g_xpb[(size_t)TT * 1536];
__device__ float g_out[(size_t)TT * 1024];     // [t][2H]  (fwd 0..511, bwd 512..1023)
__device__ float g_logits[TT];

// ---------------- helpers ----------------
__device__ __forceinline__ float fsig(float x) {
    return __fdividef(1.f, 1.f + __expf(-x));
}
__device__ __forceinline__ float ftanh_fast(float x) {
    float t = __expf(-2.f * x);
    return __fdividef(1.f - t, 1.f + t);
}
__device__ __forceinline__ unsigned smem_u32(const void* p) {
    unsigned a;
    asm("{ .reg .u64 t; cvta.to.shared.u64 t, %1; cvt.u32.u64 %0, t; }" : "=r"(a) : "l"(p));
    return a;
}
__device__ __forceinline__ unsigned long long lds_vol_u64(unsigned a) {
    unsigned long long v;
    asm volatile("ld.volatile.shared.u64 %0, [%1];" : "=l"(v) : "r"(a));
    return v;
}
__device__ __forceinline__ void fma2(unsigned long long& acc, unsigned long long a,
                                     unsigned long long b) {
    asm("fma.rn.f32x2 %0, %1, %2, %0;" : "+l"(acc) : "l"(a), "l"(b));
}

// ---------------- e[t] = dot(query[t], fc_w) + fc_b ----------------
__global__ void k_e(const float* __restrict__ q, const float* __restrict__ fcw,
                    const float* __restrict__ fcb) {
    int t = blockIdx.x * 8 + (threadIdx.x >> 5);
    int l = threadIdx.x & 31;
    const float* row = q + (size_t)t * EE;
    float s = 0.f;
    #pragma unroll
    for (int i = 0; i < 16; i++) s += row[l + 32 * i] * fcw[l + 32 * i];
    #pragma unroll
    for (int o = 16; o; o >>= 1) s += __shfl_down_sync(0xffffffffu, s, o);
    if (l == 0) g_e[t] = s + fcb[0];
}

// ---------------- energy: zero fill WITH fused diagonal (after the GRU) ----------
__global__ void k_zero(float* __restrict__ out, int n4) {
    float4* p = (float4*)(out + 1024);
    int stride = gridDim.x * blockDim.x;
    for (int i = blockIdx.x * blockDim.x + threadIdx.x; i < n4; i += stride) {
        float4 z = make_float4(0.f, 0.f, 0.f, 0.f);
        unsigned base = 4u * (unsigned)i;               // element index in 4096x4096 plane
        unsigned d = (base + 4096u) / 4097u;            // ceil(base/4097)
        unsigned pos = d * 4097u;                       // candidate diagonal element
        if (d < 4096u && pos < base + 4u) ((float*)&z)[pos - base] = g_e[d];
        p[i] = z;
    }
}

// ---------------- GEMM (8x8 thread tile): Co[t][n] = sum_k (e[t]*A[t][k])*W[n][k] + b[n] ---
// BM=128, BN=128, BK=16, 256 threads. blockIdx.z selects direction.
__global__ void __launch_bounds__(256) k_gemm2(const float* __restrict__ A,
                                               const float* __restrict__ Wf,
                                               const float* __restrict__ bf,
                                               const float* __restrict__ Wb,
                                               const float* __restrict__ bbp) {
    int which = blockIdx.z;
    const float* __restrict__ W = which ? Wb : Wf;
    const float* __restrict__ bias = which ? bbp : bf;
    float* __restrict__ Co = which ? g_xpb : g_xpf;
    __shared__ __align__(16) float As[16][128];
    __shared__ __align__(16) float Bs[16][128];
    int tid = threadIdx.x;
    int tx = tid & 15, ty = tid >> 4;
    int m0 = blockIdx.y * 128, n0 = blockIdx.x * 128;

    int aRow = tid >> 1;          // 0..127
    int aCol = (tid & 1) * 8;     // 0 or 8
    float e0 = g_e[m0 + aRow];

    float acc[8][8];
    #pragma unroll
    for (int i = 0; i < 8; i++)
        #pragma unroll
        for (int jj = 0; jj < 8; jj++) acc[i][jj] = 0.f;

    for (int k0 = 0; k0 < EE; k0 += 16) {
        float4 a0 = *(const float4*)(A + (size_t)(m0 + aRow) * EE + k0 + aCol);
        float4 a1 = *(const float4*)(A + (size_t)(m0 + aRow) * EE + k0 + aCol + 4);
        float4 b0 = *(const float4*)(W + (size_t)(n0 + aRow) * EE + k0 + aCol);
        float4 b1 = *(const float4*)(W + (size_t)(n0 + aRow) * EE + k0 + aCol + 4);
        __syncthreads();
        As[aCol + 0][aRow] = a0.x * e0; As[aCol + 1][aRow] = a0.y * e0;
        As[aCol + 2][aRow] = a0.z * e0; As[aCol + 3][aRow] = a0.w * e0;
        As[aCol + 4][aRow] = a1.x * e0; As[aCol + 5][aRow] = a1.y * e0;
        As[aCol + 6][aRow] = a1.z * e0; As[aCol + 7][aRow] = a1.w * e0;
        Bs[aCol + 0][aRow] = b0.x; Bs[aCol + 1][aRow] = b0.y;
        Bs[aCol + 2][aRow] = b0.z; Bs[aCol + 3][aRow] = b0.w;
        Bs[aCol + 4][aRow] = b1.x; Bs[aCol + 5][aRow] = b1.y;
        Bs[aCol + 6][aRow] = b1.z; Bs[aCol + 7][aRow] = b1.w;
        __syncthreads();
        #pragma unroll
        for (int kk = 0; kk < 16; kk++) {
            float4 av0 = *(float4*)&As[kk][ty * 8];
            float4 av1 = *(float4*)&As[kk][ty * 8 + 4];
            float4 bv0 = *(float4*)&Bs[kk][tx * 8];
            float4 bv1 = *(float4*)&Bs[kk][tx * 8 + 4];
            float am[8] = {av0.x, av0.y, av0.z, av0.w, av1.x, av1.y, av1.z, av1.w};
            float bn[8] = {bv0.x, bv0.y, bv0.z, bv0.w, bv1.x, bv1.y, bv1.z, bv1.w};
            #pragma unroll
            for (int i = 0; i < 8; i++)
                #pragma unroll
                for (int jj = 0; jj < 8; jj++) acc[i][jj] += am[i] * bn[jj];
        }
    }
    float bb[8];
    #pragma unroll
    for (int jj = 0; jj < 8; jj++) bb[jj] = bias[n0 + tx * 8 + jj];
    #pragma unroll
    for (int i = 0; i < 8; i++) {
        int m = m0 + ty * 8 + i;
        float4 v0 = make_float4(acc[i][0] + bb[0], acc[i][1] + bb[1],
                                acc[i][2] + bb[2], acc[i][3] + bb[3]);
        float4 v1 = make_float4(acc[i][4] + bb[4], acc[i][5] + bb[5],
                                acc[i][6] + bb[6], acc[i][7] + bb[7]);
        *(float4*)(Co + (size_t)m * 1536 + n0 + tx * 8) = v0;
        *(float4*)(Co + (size_t)m * 1536 + n0 + tx * 8 + 4) = v1;
    }
}

// ---------------- cluster GRU: DSMEM tagged push, local-SMEM poll (R7 winner, verbatim) ----
__global__ void __launch_bounds__(512, 1) __cluster_dims__(16, 1, 1)
k_gruc(const float* __restrict__ whhf, const float* __restrict__ bhhf,
       const float* __restrict__ whhb, const float* __restrict__ bhhb) {
    __shared__ unsigned long long tagbuf[2][HH];  // [parity][h]: hi=tag, lo=float bits
    __shared__ float hs[HH];

    int dir = blockIdx.x >> 4;
    unsigned rank = blockIdx.x & 15;
    const float* whh = dir ? whhb : whhf;
    const float* bhh = dir ? bhhb : bhhf;
    const float* xp  = dir ? g_xpb : g_xpf;

    int tid = threadIdx.x;
    int w = tid >> 5, l = tid & 31;
    int hw = l >> 4, l2 = l & 15;
    int j = (int)rank * 32 + 2 * w + hw;   // this half-warp's global h index

    tagbuf[0][tid] = 0ull;                     // tag 0, h=0 (state before step 0)
    tagbuf[1][tid] = 0xFFFFFFFF00000000ull;    // invalid
    __syncthreads();
    asm volatile("barrier.cluster.arrive.aligned;" ::: "memory");
    asm volatile("barrier.cluster.wait.aligned;" ::: "memory");

    // weights: lane l2 covers k = c*64 + l2*4 .. +3 (c=0..7), packed f32x2
    unsigned long long wr[3][16];
    #pragma unroll
    for (int g = 0; g < 3; g++) {
        const float* row = whh + (size_t)(g * 512 + j) * 512;
        #pragma unroll
        for (int c = 0; c < 8; c++) {
            ulonglong2 v = *(const ulonglong2*)(row + c * 64 + l2 * 4);
            wr[g][c * 2 + 0] = v.x;
            wr[g][c * 2 + 1] = v.y;
        }
    }
    float bh0 = bhh[j], bh1 = bhh[512 + j], bh2 = bhh[1024 + j];
    float hold = 0.f;

    unsigned tb_base = smem_u32(&tagbuf[0][0]);

    // prefetch xp row for t=0 (all lanes; same addr per half-warp -> broadcast)
    float xr_c, xz_c, xn_c;
    {
        const float* row0 = xp + (size_t)(dir ? (TT - 1) : 0) * 1536;
        xr_c = __ldg(row0 + j);
        xz_c = __ldg(row0 + 512 + j);
        xn_c = __ldg(row0 + 1024 + j);
    }

    for (int t = 0; t < TT; t++) {
        // issue xp loads for step t+1 now; consumed next iteration (~1 step of hiding)
        int tn = (t + 1 < TT) ? (t + 1) : t;
        const float* xprow = xp + (size_t)(dir ? (TT - 1 - tn) : tn) * 1536;
        float xr_n = __ldg(xprow + j);
        float xz_n = __ldg(xprow + 512 + j);
        float xn_n = __ldg(xprow + 1024 + j);

        // poll own slot in LOCAL smem until tag == t
        unsigned slot = tb_base + ((t & 1) ? 4096u : 0u) + (unsigned)tid * 8u;
        unsigned tg = (unsigned)t;
        unsigned long long v = lds_vol_u64(slot);
        while ((unsigned)(v >> 32) != tg) v = lds_vol_u64(slot);
        hs[tid] = __uint_as_float((unsigned)v);
        __syncthreads();

        // matvec via packed f32x2 FMA
        unsigned long long a0p = 0ull, a1p = 0ull, a2p = 0ull;
        const ulonglong2* hp = (const ulonglong2*)hs;
        #pragma unroll
        for (int c = 0; c < 8; c++) {
            ulonglong2 hv = hp[(c * 64 + l2 * 4) >> 2];
            fma2(a0p, wr[0][c*2+0], hv.x); fma2(a0p, wr[0][c*2+1], hv.y);
            fma2(a1p, wr[1][c*2+0], hv.x); fma2(a1p, wr[1][c*2+1], hv.y);
            fma2(a2p, wr[2][c*2+0], hv.x); fma2(a2p, wr[2][c*2+1], hv.y);
        }
        float a0 = __uint_as_float((unsigned)a0p) + __uint_as_float((unsigned)(a0p >> 32));
        float a1 = __uint_as_float((unsigned)a1p) + __uint_as_float((unsigned)(a1p >> 32));
        float a2 = __uint_as_float((unsigned)a2p) + __uint_as_float((unsigned)(a2p >> 32));
        // butterfly reduce width 16: ALL lanes end with the full sums
        #pragma unroll
        for (int o = 8; o; o >>= 1) {
            a0 += __shfl_xor_sync(0xffffffffu, a0, o, 16);
            a1 += __shfl_xor_sync(0xffffffffu, a1, o, 16);
            a2 += __shfl_xor_sync(0xffffffffu, a2, o, 16);
        }
        // all 16 lanes compute gates (SIMT); hold is replicated per lane
        float r = fsig(xr_c + bh0 + a0);
        float z = fsig(xz_c + bh1 + a1);
        float n = ftanh_fast(__fmaf_rn(r, a2 + bh2, xn_c));
        float hnew = __fmaf_rn(z, hold - n, n);   // (1-z)*n + z*h
        hold = hnew;
        if (t + 1 < TT) {
            // lane l2 pushes {tag t+1, hnew} to rank l2: 16-way fan-out, one instruction
            unsigned long long pv = ((unsigned long long)(unsigned)(t + 1) << 32) |
                                    (unsigned long long)__float_as_uint(hnew);
            unsigned loff = tb_base + (((t + 1) & 1) ? 4096u : 0u) + (unsigned)j * 8u;
            unsigned raddr;
            asm("mapa.shared::cluster.u32 %0, %1, %2;"
                : "=r"(raddr) : "r"(loff), "r"((unsigned)l2));
            asm volatile("st.shared::cluster.u64 [%0], %1;"
                         :: "r"(raddr), "l"(pv) : "memory");
        }
        if (l2 == 0) {
            int orow = dir ? (TT - 1 - t) : t;
            g_out[(size_t)orow * 1024 + dir * 512 + j] = hnew;
        }
        // rotate xp pipeline
        xr_c = xr_n; xz_c = xz_n; xn_c = xn_n;
        // trailing barrier: all hs reads of step t complete before any t+1 hs write;
        // also keeps warps lockstep (tighter arrival distribution at the poll).
        __syncthreads();
    }
    asm volatile("barrier.cluster.arrive.aligned;" ::: "memory");
    asm volatile("barrier.cluster.wait.aligned;" ::: "memory");
}

// ---------------- attention epilogue (fused) ----------------
// logits: hid staged in smem (hb_last = g_out[0][512..], hf_last = g_out[4095][0..512))
__global__ void k_logits() {
    __shared__ float hid[1024];
    int tid = threadIdx.x;   // 256
    for (int i = tid; i < 512; i += 256) {
        hid[i] = g_out[512 + i];                              // hb_last
        hid[512 + i] = g_out[(size_t)4095 * 1024 + i];        // hf_last
    }
    __syncthreads();
    int t = blockIdx.x * 8 + (tid >> 5);
    int l = tid & 31;
    const float* row = g_out + (size_t)t * 1024;
    float s = 0.f;
    #pragma unroll
    for (int i = 0; i < 32; i++) s += row[l + 32 * i] * hid[l + 32 * i];
    #pragma unroll
    for (int o = 16; o; o >>= 1) s += __shfl_down_sync(0xffffffffu, s, o);
    if (l == 0) g_logits[t] = s * 0.03125f;  // 1/sqrt(1024)
}

// lin with inlined softmax: each CTA re-derives max & sum over the 4096 logits (L2-hot)
__global__ void k_lin(float* __restrict__ out) {
    __shared__ float redm[8], reds[8];
    __shared__ float sm[4][64];
    int tid = threadIdx.x;   // 256
    // max
    float m = -1e30f;
    for (int i = tid; i < TT; i += 256) m = fmaxf(m, g_logits[i]);
    #pragma unroll
    for (int o = 16; o; o >>= 1) m = fmaxf(m, __shfl_xor_sync(0xffffffffu, m, o));
    if ((tid & 31) == 0) redm[tid >> 5] = m;
    __syncthreads();
    if (tid < 32) {
        float v = (tid < 8) ? redm[tid] : -1e30f;
        #pragma unroll
        for (int o = 4; o; o >>= 1) v = fmaxf(v, __shfl_xor_sync(0xffffffffu, v, o));
        if (tid == 0) redm[0] = v;
    }
    __syncthreads();
    m = redm[0];
    // sum
    float s = 0.f;
    for (int i = tid; i < TT; i += 256) s += __expf(g_logits[i] - m);
    #pragma unroll
    for (int o = 16; o; o >>= 1) s += __shfl_xor_sync(0xffffffffu, s, o);
    if ((tid & 31) == 0) reds[tid >> 5] = s;
    __syncthreads();
    if (tid < 32) {
        float v = (tid < 8) ? reds[tid] : 0.f;
        #pragma unroll
        for (int o = 4; o; o >>= 1) v += __shfl_xor_sync(0xffffffffu, v, o);
        if (tid == 0) reds[0] = v;
    }
    __syncthreads();
    float inv = __fdividef(1.f, reds[0]);
    // weighted sum
    int c = blockIdx.x;
    int jj = tid & 63;
    int rr = tid >> 6;
    int col = c * 64 + jj;
    float acc = 0.f;
    for (int t = rr; t < TT; t += 4)
        acc += __expf(g_logits[t] - m) * g_out[(size_t)t * 1024 + col];
    sm[rr][jj] = acc;
    __syncthreads();
    if (rr == 0) out[col] = (sm[0][jj] + sm[1][jj] + sm[2][jj] + sm[3][jj]) * inv;
}

// ---------------- launch ----------------
extern "C" void kernel_launch(void* const* d_in, const int* in_sizes, int n_in,
                              void* d_out, int out_size) {
    const float* input = (const float*)d_in[0];
    const float* query = (const float*)d_in[1];
    const float* fc_w  = (const float*)d_in[2];
    const float* fc_b  = (const float*)d_in[3];
    const float* wihf  = (const float*)d_in[4];
    const float* whhf  = (const float*)d_in[5];
    const float* bihf  = (const float*)d_in[6];
    const float* bhhf  = (const float*)d_in[7];
    const float* wihb  = (const float*)d_in[8];
    const float* whhb  = (const float*)d_in[9];
    const float* bihb  = (const float*)d_in[10];
    const float* bhhb  = (const float*)d_in[11];
    float* out = (float*)d_out;

    int n4 = (out_size - 1024) / 4;  // energy float4 count

    cudaFuncSetAttribute(k_gruc, cudaFuncAttributeNonPortableClusterSizeAllowed, 1);

    k_e<<<TT / 8, 256>>>(query, fc_w, fc_b);
    dim3 gg(1536 / 128, TT / 128, 2);
    k_gemm2<<<gg, 256>>>(input, wihf, bihf, wihb, bihb);
    k_gruc<<<32, 512>>>(whhf, bhhf, whhb, bhhb);   // GRU owns the chip; xp L2-hot
    k_zero<<<4096, 256>>>(out, n4);                // zero + diagonal fused, after the GRU
    k_logits<<<TT / 8, 256>>>();
    k_lin<<<16, 256>>>(out);
}

// round 11
// speedup vs baseline: 1.5086x; 1.0473x over previous
#include <cuda_runtime.h>
#include <math.h>

#define TT 4096
#define EE 512
#define HH 512

// ---------------- scratch (static device globals; no allocation) ----------------
__device__ float g_e[TT];
__device__ float g_xpf[(size_t)TT * 1536];
__device__ float g_xpb[(size_t)TT * 1536];
__device__ float g_out[(size_t)TT * 1024];     // [t][2H]  (fwd 0..511, bwd 512..1023)
__device__ float g_logits[TT];

// ---------------- helpers ----------------
__device__ __forceinline__ float htanh(float x) {      // HW tanh: single MUFU op
    float y;
    asm("tanh.approx.f32 %0, %1;" : "=f"(y) : "f"(x));
    return y;
}
__device__ __forceinline__ unsigned smem_u32(const void* p) {
    unsigned a;
    asm("{ .reg .u64 t; cvta.to.shared.u64 t, %1; cvt.u32.u64 %0, t; }" : "=r"(a) : "l"(p));
    return a;
}
__device__ __forceinline__ unsigned long long lds_vol_u64(unsigned a) {
    unsigned long long v;
    asm volatile("ld.volatile.shared.u64 %0, [%1];" : "=l"(v) : "r"(a));
    return v;
}
__device__ __forceinline__ void fma2(unsigned long long& acc, unsigned long long a,
                                     unsigned long long b) {
    asm("fma.rn.f32x2 %0, %1, %2, %0;" : "+l"(acc) : "l"(a), "l"(b));
}

// ---------------- e[t] = dot(query[t], fc_w) + fc_b ----------------
__global__ void k_e(const float* __restrict__ q, const float* __restrict__ fcw,
                    const float* __restrict__ fcb) {
    int t = blockIdx.x * 8 + (threadIdx.x >> 5);
    int l = threadIdx.x & 31;
    const float* row = q + (size_t)t * EE;
    float s = 0.f;
    #pragma unroll
    for (int i = 0; i < 16; i++) s += row[l + 32 * i] * fcw[l + 32 * i];
    #pragma unroll
    for (int o = 16; o; o >>= 1) s += __shfl_down_sync(0xffffffffu, s, o);
    if (l == 0) g_e[t] = s + fcb[0];
}

// ---------------- energy: zero fill WITH fused diagonal (after the GRU) ----------
__global__ void k_zero(float* __restrict__ out, int n4) {
    float4* p = (float4*)(out + 1024);
    int stride = gridDim.x * blockDim.x;
    for (int i = blockIdx.x * blockDim.x + threadIdx.x; i < n4; i += stride) {
        float4 z = make_float4(0.f, 0.f, 0.f, 0.f);
        unsigned base = 4u * (unsigned)i;               // element index in 4096x4096 plane
        unsigned d = (base + 4096u) / 4097u;            // ceil(base/4097)
        unsigned pos = d * 4097u;                       // candidate diagonal element
        if (d < 4096u && pos < base + 4u) ((float*)&z)[pos - base] = g_e[d];
        p[i] = z;
    }
}

// ---------------- GEMM (R7-exact 8x4): Co[t][n] = sum_k (e[t]*A[t][k])*W[n][k] + b[n] ------
// BM=128, BN=64, BK=16, 256 threads, thread tile 8x4. blockIdx.z selects direction.
__global__ void __launch_bounds__(256) k_gemm2(const float* __restrict__ A,
                                               const float* __restrict__ Wf,
                                               const float* __restrict__ bf,
                                               const float* __restrict__ Wb,
                                               const float* __restrict__ bbp) {
    int which = blockIdx.z;
    const float* __restrict__ W = which ? Wb : Wf;
    const float* __restrict__ bias = which ? bbp : bf;
    float* __restrict__ Co = which ? g_xpb : g_xpf;
    __shared__ float As[16][128];
    __shared__ float Bs[16][64];
    int tid = threadIdx.x;
    int tx = tid & 15, ty = tid >> 4;
    int m0 = blockIdx.y * 128, n0 = blockIdx.x * 64;

    int aRow = tid >> 2;
    int aCol = (tid & 3) * 4;
    float e0 = g_e[m0 + aRow];
    float e1 = g_e[m0 + aRow + 64];

    float acc[8][4];
    #pragma unroll
    for (int i = 0; i < 8; i++)
        #pragma unroll
        for (int j = 0; j < 4; j++) acc[i][j] = 0.f;

    for (int k0 = 0; k0 < EE; k0 += 16) {
        float4 a0 = *(const float4*)(A + (size_t)(m0 + aRow) * EE + k0 + aCol);
        float4 a1 = *(const float4*)(A + (size_t)(m0 + aRow + 64) * EE + k0 + aCol);
        float4 b0 = *(const float4*)(W + (size_t)(n0 + aRow) * EE + k0 + aCol);
        __syncthreads();
        As[aCol + 0][aRow] = a0.x * e0; As[aCol + 1][aRow] = a0.y * e0;
        As[aCol + 2][aRow] = a0.z * e0; As[aCol + 3][aRow] = a0.w * e0;
        As[aCol + 0][aRow + 64] = a1.x * e1; As[aCol + 1][aRow + 64] = a1.y * e1;
        As[aCol + 2][aRow + 64] = a1.z * e1; As[aCol + 3][aRow + 64] = a1.w * e1;
        Bs[aCol + 0][aRow] = b0.x; Bs[aCol + 1][aRow] = b0.y;
        Bs[aCol + 2][aRow] = b0.z; Bs[aCol + 3][aRow] = b0.w;
        __syncthreads();
        #pragma unroll
        for (int kk = 0; kk < 16; kk++) {
            float4 av0 = *(float4*)&As[kk][ty * 8];
            float4 av1 = *(float4*)&As[kk][ty * 8 + 4];
            float4 bv  = *(float4*)&Bs[kk][tx * 4];
            float av[8] = {av0.x, av0.y, av0.z, av0.w, av1.x, av1.y, av1.z, av1.w};
            float bbv[4] = {bv.x, bv.y, bv.z, bv.w};
            #pragma unroll
            for (int i = 0; i < 8; i++)
                #pragma unroll
                for (int j = 0; j < 4; j++) acc[i][j] += av[i] * bbv[j];
        }
    }
    float bb0 = bias[n0 + tx * 4 + 0], bb1 = bias[n0 + tx * 4 + 1];
    float bb2 = bias[n0 + tx * 4 + 2], bb3 = bias[n0 + tx * 4 + 3];
    #pragma unroll
    for (int i = 0; i < 8; i++) {
        int m = m0 + ty * 8 + i;
        float4 v = make_float4(acc[i][0] + bb0, acc[i][1] + bb1,
                               acc[i][2] + bb2, acc[i][3] + bb3);
        *(float4*)(Co + (size_t)m * 1536 + n0 + tx * 4) = v;
    }
}

// ---------------- cluster GRU: R7 winner + HW-tanh gates ----------------
// grid = 32 CTAs, cluster(16): blocks 0-15 = forward, 16-31 = backward.
// Only change vs the 4472us winner: gate nonlinearities use tanh.approx.f32
// (sigmoid(x) = 0.5*tanh(x/2)+0.5), with bias and the x0.5 factor folded into the
// xp prefetch rotation (off the critical path).
__global__ void __launch_bounds__(512, 1) __cluster_dims__(16, 1, 1)
k_gruc(const float* __restrict__ whhf, const float* __restrict__ bhhf,
       const float* __restrict__ whhb, const float* __restrict__ bhhb) {
    __shared__ unsigned long long tagbuf[2][HH];  // [parity][h]: hi=tag, lo=float bits
    __shared__ float hs[HH];

    int dir = blockIdx.x >> 4;
    unsigned rank = blockIdx.x & 15;
    const float* whh = dir ? whhb : whhf;
    const float* bhh = dir ? bhhb : bhhf;
    const float* xp  = dir ? g_xpb : g_xpf;

    int tid = threadIdx.x;
    int w = tid >> 5, l = tid & 31;
    int hw = l >> 4, l2 = l & 15;
    int j = (int)rank * 32 + 2 * w + hw;   // this half-warp's global h index

    tagbuf[0][tid] = 0ull;                     // tag 0, h=0 (state before step 0)
    tagbuf[1][tid] = 0xFFFFFFFF00000000ull;    // invalid
    __syncthreads();
    asm volatile("barrier.cluster.arrive.aligned;" ::: "memory");
    asm volatile("barrier.cluster.wait.aligned;" ::: "memory");

    // weights: lane l2 covers k = c*64 + l2*4 .. +3 (c=0..7), packed f32x2
    unsigned long long wr[3][16];
    #pragma unroll
    for (int g = 0; g < 3; g++) {
        const float* row = whh + (size_t)(g * 512 + j) * 512;
        #pragma unroll
        for (int c = 0; c < 8; c++) {
            ulonglong2 v = *(const ulonglong2*)(row + c * 64 + l2 * 4);
            wr[g][c * 2 + 0] = v.x;
            wr[g][c * 2 + 1] = v.y;
        }
    }
    float bh0 = bhh[j], bh1 = bhh[512 + j], bh2 = bhh[1024 + j];
    float hold = 0.f;

    unsigned tb_base = smem_u32(&tagbuf[0][0]);

    // prefetch xp row for t=0; fold biases + 0.5 factor (off critical path)
    float xr_c, xz_c, xn_c;
    {
        const float* row0 = xp + (size_t)(dir ? (TT - 1) : 0) * 1536;
        xr_c = (__ldg(row0 + j) + bh0) * 0.5f;
        xz_c = (__ldg(row0 + 512 + j) + bh1) * 0.5f;
        xn_c = __ldg(row0 + 1024 + j);
    }

    for (int t = 0; t < TT; t++) {
        // issue xp loads for step t+1 now; consumed next iteration (~1 step of hiding)
        int tn = (t + 1 < TT) ? (t + 1) : t;
        const float* xprow = xp + (size_t)(dir ? (TT - 1 - tn) : tn) * 1536;
        float xr_n = __ldg(xprow + j);
        float xz_n = __ldg(xprow + 512 + j);
        float xn_n = __ldg(xprow + 1024 + j);

        // poll own slot in LOCAL smem until tag == t
        unsigned slot = tb_base + ((t & 1) ? 4096u : 0u) + (unsigned)tid * 8u;
        unsigned tg = (unsigned)t;
        unsigned long long v = lds_vol_u64(slot);
        while ((unsigned)(v >> 32) != tg) v = lds_vol_u64(slot);
        hs[tid] = __uint_as_float((unsigned)v);
        __syncthreads();

        // matvec via packed f32x2 FMA
        unsigned long long a0p = 0ull, a1p = 0ull, a2p = 0ull;
        const ulonglong2* hp = (const ulonglong2*)hs;
        #pragma unroll
        for (int c = 0; c < 8; c++) {
            ulonglong2 hv = hp[(c * 64 + l2 * 4) >> 2];
            fma2(a0p, wr[0][c*2+0], hv.x); fma2(a0p, wr[0][c*2+1], hv.y);
            fma2(a1p, wr[1][c*2+0], hv.x); fma2(a1p, wr[1][c*2+1], hv.y);
            fma2(a2p, wr[2][c*2+0], hv.x); fma2(a2p, wr[2][c*2+1], hv.y);
        }
        float a0 = __uint_as_float((unsigned)a0p) + __uint_as_float((unsigned)(a0p >> 32));
        float a1 = __uint_as_float((unsigned)a1p) + __uint_as_float((unsigned)(a1p >> 32));
        float a2 = __uint_as_float((unsigned)a2p) + __uint_as_float((unsigned)(a2p >> 32));
        // butterfly reduce width 16: ALL lanes end with the full sums
        #pragma unroll
        for (int o = 8; o; o >>= 1) {
            a0 += __shfl_xor_sync(0xffffffffu, a0, o, 16);
            a1 += __shfl_xor_sync(0xffffffffu, a1, o, 16);
            a2 += __shfl_xor_sync(0xffffffffu, a2, o, 16);
        }
        // HW-tanh gates: sigmoid(x) = 0.5*tanh(x/2)+0.5
        // chain: FFMA -> MUFU -> FFMA (r) -> FFMA -> MUFU (n) -> FADD+FFMA (hnew)
        float r = __fmaf_rn(0.5f, htanh(__fmaf_rn(0.5f, a0, xr_c)), 0.5f);
        float z = __fmaf_rn(0.5f, htanh(__fmaf_rn(0.5f, a1, xz_c)), 0.5f);
        float n = htanh(__fmaf_rn(r, a2 + bh2, xn_c));
        float hnew = __fmaf_rn(z, hold - n, n);   // (1-z)*n + z*h
        hold = hnew;
        if (t + 1 < TT) {
            // lane l2 pushes {tag t+1, hnew} to rank l2: 16-way fan-out, one instruction
            unsigned long long pv = ((unsigned long long)(unsigned)(t + 1) << 32) |
                                    (unsigned long long)__float_as_uint(hnew);
            unsigned loff = tb_base + (((t + 1) & 1) ? 4096u : 0u) + (unsigned)j * 8u;
            unsigned raddr;
            asm("mapa.shared::cluster.u32 %0, %1, %2;"
                : "=r"(raddr) : "r"(loff), "r"((unsigned)l2));
            asm volatile("st.shared::cluster.u64 [%0], %1;"
                         :: "r"(raddr), "l"(pv) : "memory");
        }
        if (l2 == 0) {
            int orow = dir ? (TT - 1 - t) : t;
            g_out[(size_t)orow * 1024 + dir * 512 + j] = hnew;
        }
        // rotate xp pipeline, folding biases + 0.5 (off critical path)
        xr_c = (xr_n + bh0) * 0.5f;
        xz_c = (xz_n + bh1) * 0.5f;
        xn_c = xn_n;
        // trailing barrier: all hs reads of step t complete before any t+1 hs write;
        // also keeps warps lockstep (tighter arrival distribution at the poll).
        __syncthreads();
    }
    asm volatile("barrier.cluster.arrive.aligned;" ::: "memory");
    asm volatile("barrier.cluster.wait.aligned;" ::: "memory");
}

// ---------------- attention epilogue (fused) ----------------
__global__ void k_logits() {
    __shared__ float hid[1024];
    int tid = threadIdx.x;   // 256
    for (int i = tid; i < 512; i += 256) {
        hid[i] = g_out[512 + i];                              // hb_last
        hid[512 + i] = g_out[(size_t)4095 * 1024 + i];        // hf_last
    }
    __syncthreads();
    int t = blockIdx.x * 8 + (tid >> 5);
    int l = tid & 31;
    const float* row = g_out + (size_t)t * 1024;
    float s = 0.f;
    #pragma unroll
    for (int i = 0; i < 32; i++) s += row[l + 32 * i] * hid[l + 32 * i];
    #pragma unroll
    for (int o = 16; o; o >>= 1) s += __shfl_down_sync(0xffffffffu, s, o);
    if (l == 0) g_logits[t] = s * 0.03125f;  // 1/sqrt(1024)
}

// lin with inlined softmax: each CTA re-derives max & sum over the 4096 logits (L2-hot)
__global__ void k_lin(float* __restrict__ out) {
    __shared__ float redm[8], reds[8];
    __shared__ float sm[4][64];
    int tid = threadIdx.x;   // 256
    float m = -1e30f;
    for (int i = tid; i < TT; i += 256) m = fmaxf(m, g_logits[i]);
    #pragma unroll
    for (int o = 16; o; o >>= 1) m = fmaxf(m, __shfl_xor_sync(0xffffffffu, m, o));
    if ((tid & 31) == 0) redm[tid >> 5] = m;
    __syncthreads();
    if (tid < 32) {
        float v = (tid < 8) ? redm[tid] : -1e30f;
        #pragma unroll
        for (int o = 4; o; o >>= 1) v = fmaxf(v, __shfl_xor_sync(0xffffffffu, v, o));
        if (tid == 0) redm[0] = v;
    }
    __syncthreads();
    m = redm[0];
    float s = 0.f;
    for (int i = tid; i < TT; i += 256) s += __expf(g_logits[i] - m);
    #pragma unroll
    for (int o = 16; o; o >>= 1) s += __shfl_xor_sync(0xffffffffu, s, o);
    if ((tid & 31) == 0) reds[tid >> 5] = s;
    __syncthreads();
    if (tid < 32) {
        float v = (tid < 8) ? reds[tid] : 0.f;
        #pragma unroll
        for (int o = 4; o; o >>= 1) v += __shfl_xor_sync(0xffffffffu, v, o);
        if (tid == 0) reds[0] = v;
    }
    __syncthreads();
    float inv = __fdividef(1.f, reds[0]);
    int c = blockIdx.x;
    int jj = tid & 63;
    int rr = tid >> 6;
    int col = c * 64 + jj;
    float acc = 0.f;
    for (int t = rr; t < TT; t += 4)
        acc += __expf(g_logits[t] - m) * g_out[(size_t)t * 1024 + col];
    sm[rr][jj] = acc;
    __syncthreads();
    if (rr == 0) out[col] = (sm[0][jj] + sm[1][jj] + sm[2][jj] + sm[3][jj]) * inv;
}

// ---------------- launch ----------------
extern "C" void kernel_launch(void* const* d_in, const int* in_sizes, int n_in,
                              void* d_out, int out_size) {
    const float* input = (const float*)d_in[0];
    const float* query = (const float*)d_in[1];
    const float* fc_w  = (const float*)d_in[2];
    const float* fc_b  = (const float*)d_in[3];
    const float* wihf  = (const float*)d_in[4];
    const float* whhf  = (const float*)d_in[5];
    const float* bihf  = (const float*)d_in[6];
    const float* bhhf  = (const float*)d_in[7];
    const float* wihb  = (const float*)d_in[8];
    const float* whhb  = (const float*)d_in[9];
    const float* bihb  = (const float*)d_in[10];
    const float* bhhb  = (const float*)d_in[11];
    float* out = (float*)d_out;

    int n4 = (out_size - 1024) / 4;  // energy float4 count

    cudaFuncSetAttribute(k_gruc, cudaFuncAttributeNonPortableClusterSizeAllowed, 1);

    k_e<<<TT / 8, 256>>>(query, fc_w, fc_b);
    dim3 gg(1536 / 64, TT / 128, 2);
    k_gemm2<<<gg, 256>>>(input, wihf, bihf, wihb, bihb);
    k_gruc<<<32, 512>>>(whhf, bhhf, whhb, bhhb);   // GRU owns the chip; xp L2-hot
    k_zero<<<4096, 256>>>(out, n4);                // zero + diagonal fused, after the GRU
    k_logits<<<TT / 8, 256>>>();
    k_lin<<<16, 256>>>(out);
}